// round 1
// baseline (speedup 1.0000x reference)
#include <cuda_runtime.h>
#include <cstdint>

#define B 64
#define T 50
#define D 512
#define H 1024
#define V 32000
#define G3 3072   // 3*H

// ---------------- scratch (no allocations allowed) ----------------
__device__ float g_h[B * H];
__device__ float g_gi[B * G3];
__device__ float g_gh[B * G3];
__device__ unsigned long long g_packed[B];

// ---------------- threefry2x32 (exact JAX rotation/key schedule) ----------------
__device__ __forceinline__ void tf2x32(uint32_t k0, uint32_t k1, uint32_t x0, uint32_t x1,
                                       uint32_t& o0, uint32_t& o1) {
    uint32_t ks2 = k0 ^ k1 ^ 0x1BD11BDAu;
    x0 += k0; x1 += k1;
#define RND(r) { x0 += x1; x1 = __funnelshift_l(x1, x1, (r)); x1 ^= x0; }
    RND(13) RND(15) RND(26) RND(6)   x0 += k1;  x1 += ks2 + 1u;
    RND(17) RND(29) RND(16) RND(24)  x0 += ks2; x1 += k0  + 2u;
    RND(13) RND(15) RND(26) RND(6)   x0 += k0;  x1 += k1  + 3u;
    RND(17) RND(29) RND(16) RND(24)  x0 += k1;  x1 += ks2 + 4u;
    RND(13) RND(15) RND(26) RND(6)   x0 += ks2; x1 += k0  + 5u;
#undef RND
    o0 = x0; o1 = x1;
}

static inline uint32_t h_rotl(uint32_t v, int d) { return (v << d) | (v >> (32 - d)); }
static void tf2x32_host(uint32_t k0, uint32_t k1, uint32_t x0, uint32_t x1,
                        uint32_t* o0, uint32_t* o1) {
    uint32_t ks2 = k0 ^ k1 ^ 0x1BD11BDAu;
    const int rA[4] = {13, 15, 26, 6}, rB[4] = {17, 29, 16, 24};
    x0 += k0; x1 += k1;
    for (int i = 0; i < 4; i++) { x0 += x1; x1 = h_rotl(x1, rA[i]); x1 ^= x0; }
    x0 += k1;  x1 += ks2 + 1u;
    for (int i = 0; i < 4; i++) { x0 += x1; x1 = h_rotl(x1, rB[i]); x1 ^= x0; }
    x0 += ks2; x1 += k0 + 2u;
    for (int i = 0; i < 4; i++) { x0 += x1; x1 = h_rotl(x1, rA[i]); x1 ^= x0; }
    x0 += k0;  x1 += k1 + 3u;
    for (int i = 0; i < 4; i++) { x0 += x1; x1 = h_rotl(x1, rB[i]); x1 ^= x0; }
    x0 += k1;  x1 += ks2 + 4u;
    for (int i = 0; i < 4; i++) { x0 += x1; x1 = h_rotl(x1, rA[i]); x1 ^= x0; }
    x0 += ks2; x1 += k0 + 5u;
    *o0 = x0; *o1 = x1;
}

// ---------------- GRU gemm: gi = x@Wih^T + b_ih ; gh = h@Whh^T + b_hh ----------------
// Grid 96 blocks x 256 threads. Block tile: 64 b x 32 g rows, K = 512(x) + 1024(h).
__global__ void __launch_bounds__(256) gru_gemm_kernel(
    int t, const float* __restrict__ seq_emb, const float* __restrict__ emb,
    const float* __restrict__ Wih, const float* __restrict__ Whh,
    const float* __restrict__ bih, const float* __restrict__ bhh,
    const int* __restrict__ eosp)
{
    __shared__ float sA[64][68];
    __shared__ float sW[64][36];
    __shared__ int sIdx[B];
    int tid = threadIdx.x;
    int g0 = blockIdx.x * 32;

    if (tid < B) {
        int idx;
        if (t == 0) idx = eosp[0];
        else idx = (int)(0x7FFFFFFFu - (unsigned)(g_packed[tid] & 0xFFFFFFFFull));
        sIdx[tid] = idx;
    }
    __syncthreads();

    const float* hin = (t == 0) ? seq_emb : g_h;

    float accI[4][2] = {{0.f,0.f},{0.f,0.f},{0.f,0.f},{0.f,0.f}};
    float accH[4][2] = {{0.f,0.f},{0.f,0.f},{0.f,0.f},{0.f,0.f}};
    int gl0 = (tid & 15) * 2;
    int b0  = (tid >> 4) * 4;

    for (int c = 0; c < 24; c++) {
        int kb = c * 64;
        #pragma unroll
        for (int i = 0; i < 16; i++) {
            int e = tid + i * 256;
            int b = e >> 6, kk = e & 63;
            int kg = kb + kk;
            float v;
            if (kg < 512) v = emb[(size_t)sIdx[b] * D + kg];
            else          v = hin[b * H + (kg - 512)];
            sA[kk][b] = v;
        }
        #pragma unroll
        for (int i = 0; i < 8; i++) {
            int e = tid + i * 256;
            int gl = e >> 6, kk = e & 63;
            int g = g0 + gl;
            int kg = kb + kk;
            float v;
            if (kg < 512) v = Wih[(size_t)g * D + kg];
            else          v = Whh[(size_t)g * H + (kg - 512)];
            sW[kk][gl] = v;
        }
        __syncthreads();
        if (c < 8) {
            #pragma unroll
            for (int kk = 0; kk < 64; kk++) {
                float4 a = *(const float4*)&sA[kk][b0];
                float2 w = *(const float2*)&sW[kk][gl0];
                accI[0][0] += a.x * w.x; accI[0][1] += a.x * w.y;
                accI[1][0] += a.y * w.x; accI[1][1] += a.y * w.y;
                accI[2][0] += a.z * w.x; accI[2][1] += a.z * w.y;
                accI[3][0] += a.w * w.x; accI[3][1] += a.w * w.y;
            }
        } else {
            #pragma unroll
            for (int kk = 0; kk < 64; kk++) {
                float4 a = *(const float4*)&sA[kk][b0];
                float2 w = *(const float2*)&sW[kk][gl0];
                accH[0][0] += a.x * w.x; accH[0][1] += a.x * w.y;
                accH[1][0] += a.y * w.x; accH[1][1] += a.y * w.y;
                accH[2][0] += a.z * w.x; accH[2][1] += a.z * w.y;
                accH[3][0] += a.w * w.x; accH[3][1] += a.w * w.y;
            }
        }
        __syncthreads();
    }

    #pragma unroll
    for (int q = 0; q < 2; q++) {
        int g = g0 + gl0 + q;
        float bi = bih[g], bh = bhh[g];
        #pragma unroll
        for (int i = 0; i < 4; i++) {
            int b = b0 + i;
            g_gi[b * G3 + g] = accI[i][q] + bi;
            g_gh[b * G3 + g] = accH[i][q] + bh;
        }
    }
}

// ---------------- gate update + packed reset ----------------
__global__ void __launch_bounds__(256) gru_gate_kernel(int t, const float* __restrict__ seq_emb) {
    int id = blockIdx.x * 256 + threadIdx.x;   // 65536 threads
    int b = id >> 10, j = id & 1023;
    const float* hin = (t == 0) ? seq_emb : g_h;
    float ir = g_gi[b * G3 + j],        hr = g_gh[b * G3 + j];
    float iz = g_gi[b * G3 + 1024 + j], hz = g_gh[b * G3 + 1024 + j];
    float inn= g_gi[b * G3 + 2048 + j], hn = g_gh[b * G3 + 2048 + j];
    float r = 1.f / (1.f + expf(-(ir + hr)));
    float z = 1.f / (1.f + expf(-(iz + hz)));
    float n = tanhf(inn + r * hn);
    float h = (1.f - z) * n + z * hin[b * H + j];
    g_h[b * H + j] = h;
    if (id < B) g_packed[id] = 0ull;
}

// ---------------- logits GEMM + gumbel + argmax ----------------
// Grid 250 blocks x 256 threads. Block tile 64 b x 128 v; thread 8 b x 4 v.
__global__ void __launch_bounds__(256) logits_kernel(
    int t, const float* __restrict__ fcw, const float* __restrict__ fcb,
    float* __restrict__ out, uint32_t k0, uint32_t k1)
{
    __shared__ float sH[32][68];
    __shared__ float sW[32][132];
    int tid = threadIdx.x;
    int vblk = blockIdx.x * 128;
    int b0  = (tid >> 5) * 8;
    int v0l = (tid & 31) * 4;

    float4 acc[8];
    #pragma unroll
    for (int i = 0; i < 8; i++) acc[i] = make_float4(0.f, 0.f, 0.f, 0.f);

    for (int c = 0; c < 32; c++) {
        int kb = c * 32;
        #pragma unroll
        for (int i = 0; i < 8; i++) {
            int e = tid + i * 256;
            int b = e >> 5, kk = e & 31;
            sH[kk][b] = g_h[b * H + kb + kk];
        }
        #pragma unroll
        for (int i = 0; i < 4; i++) {
            int e = tid + i * 256;
            int v = e >> 3, q = e & 7;
            float4 w = *(const float4*)&fcw[(size_t)(vblk + v) * H + kb + q * 4];
            sW[q * 4 + 0][v] = w.x; sW[q * 4 + 1][v] = w.y;
            sW[q * 4 + 2][v] = w.z; sW[q * 4 + 3][v] = w.w;
        }
        __syncthreads();
        #pragma unroll
        for (int kk = 0; kk < 32; kk++) {
            float4 w  = *(const float4*)&sW[kk][v0l];
            float4 a0 = *(const float4*)&sH[kk][b0];
            float4 a1 = *(const float4*)&sH[kk][b0 + 4];
            acc[0].x += a0.x*w.x; acc[0].y += a0.x*w.y; acc[0].z += a0.x*w.z; acc[0].w += a0.x*w.w;
            acc[1].x += a0.y*w.x; acc[1].y += a0.y*w.y; acc[1].z += a0.y*w.z; acc[1].w += a0.y*w.w;
            acc[2].x += a0.z*w.x; acc[2].y += a0.z*w.y; acc[2].z += a0.z*w.z; acc[2].w += a0.z*w.w;
            acc[3].x += a0.w*w.x; acc[3].y += a0.w*w.y; acc[3].z += a0.w*w.z; acc[3].w += a0.w*w.w;
            acc[4].x += a1.x*w.x; acc[4].y += a1.x*w.y; acc[4].z += a1.x*w.z; acc[4].w += a1.x*w.w;
            acc[5].x += a1.y*w.x; acc[5].y += a1.y*w.y; acc[5].z += a1.y*w.z; acc[5].w += a1.y*w.w;
            acc[6].x += a1.z*w.x; acc[6].y += a1.z*w.y; acc[6].z += a1.z*w.z; acc[6].w += a1.z*w.w;
            acc[7].x += a1.w*w.x; acc[7].y += a1.w*w.y; acc[7].z += a1.w*w.z; acc[7].w += a1.w*w.w;
        }
        __syncthreads();
    }

    float4 bias = *(const float4*)&fcb[vblk + v0l];
    #pragma unroll
    for (int i = 0; i < 8; i++) {
        acc[i].x += bias.x; acc[i].y += bias.y; acc[i].z += bias.z; acc[i].w += bias.w;
    }

    float* outL = out + 3200 + (size_t)t * (B * V);
    #pragma unroll
    for (int i = 0; i < 8; i++) {
        int b = b0 + i;
        *(float4*)&outL[(size_t)b * V + vblk + v0l] = acc[i];
    }

    // Gumbel-max epilogue. JAX partitionable threefry: bits[i] = o0^o1 of tf(key, (0, i)), i = b*V+v.
    #pragma unroll
    for (int i = 0; i < 8; i++) {
        int b = b0 + i;
        float vals[4] = {acc[i].x, acc[i].y, acc[i].z, acc[i].w};
        unsigned long long p = 0ull;
        #pragma unroll
        for (int j = 0; j < 4; j++) {
            int vg = vblk + v0l + j;
            unsigned cnt = (unsigned)(b * V + vg);
            uint32_t o0, o1;
            tf2x32(k0, k1, 0u, cnt, o0, o1);
            uint32_t bits = o0 ^ o1;
            float f = __uint_as_float((bits >> 9) | 0x3f800000u) - 1.0f;
            float u = fmaxf(f, 1.17549435e-38f);
            float gmb = -logf(-logf(u));
            float val = vals[j] + gmb;
            unsigned s = __float_as_uint(val);
            unsigned ord = (s & 0x80000000u) ? ~s : (s | 0x80000000u);
            unsigned long long pj = ((unsigned long long)ord << 32)
                                  | (unsigned long long)(0x7FFFFFFFu - (unsigned)vg);
            if (pj > p) p = pj;
        }
        #pragma unroll
        for (int off = 16; off; off >>= 1) {
            unsigned long long q = __shfl_down_sync(0xFFFFFFFFu, p, off);
            if (q > p) p = q;
        }
        if ((tid & 31) == 0) atomicMax(&g_packed[b], p);
    }
}

// ---------------- sample: packed -> index output ----------------
__global__ void sample_kernel(int t, float* __restrict__ out) {
    int b = threadIdx.x;
    unsigned long long p = g_packed[b];
    int v = (int)(0x7FFFFFFFu - (unsigned)(p & 0xFFFFFFFFull));
    out[t * B + b] = (float)v;
}

// ---------------- launch ----------------
extern "C" void kernel_launch(void* const* d_in, const int* in_sizes, int n_in,
                              void* d_out, int out_size) {
    (void)in_sizes; (void)n_in; (void)out_size;
    const float* seq = (const float*)d_in[0];
    const float* emb = (const float*)d_in[1];
    const float* Wih = (const float*)d_in[2];
    const float* Whh = (const float*)d_in[3];
    const float* bih = (const float*)d_in[4];
    const float* bhh = (const float*)d_in[5];
    const float* fcw = (const float*)d_in[6];
    const float* fcb = (const float*)d_in[7];
    const int*   eos = (const int*)d_in[8];
    float* out = (float*)d_out;

    // keys: jax.random.split(key(42), 50), partitionable (fold-like):
    // key_t = threefry2x32((0,42), (0, t))
    uint32_t keys[T][2];
    for (int t = 0; t < T; t++) {
        uint32_t a, b;
        tf2x32_host(0u, 42u, 0u, (uint32_t)t, &a, &b);
        keys[t][0] = a; keys[t][1] = b;
    }

    for (int t = 0; t < T; t++) {
        gru_gemm_kernel<<<96, 256>>>(t, seq, emb, Wih, Whh, bih, bhh, eos);
        gru_gate_kernel<<<256, 256>>>(t, seq);
        logits_kernel<<<250, 256>>>(t, fcw, fcb, out, keys[t][0], keys[t][1]);
        sample_kernel<<<1, 64>>>(t, out);
    }
}